// round 10
// baseline (speedup 1.0000x reference)
#include <cuda_runtime.h>
#include <cuda_fp16.h>
#include <cstdint>

#define BN 16
#define QN 256
#define KN 256
#define DN 256
#define HN 256
#define TQ 8
#define H2 (HN/2)

// scratch (device globals: no allocation allowed) — both projections half,
// row-major [row][h] with h contiguous (q row = (b,q), k row = (b,kj)).
__device__ __half g_qproj[BN * QN * HN];
__device__ __half g_kproj[BN * KN * HN];

__device__ __forceinline__ __half2 htanh2(__half2 x) {
    unsigned r, xi = *(unsigned*)&x;
    asm("tanh.approx.f16x2 %0, %1;" : "=r"(r) : "r"(xi));
    return *(__half2*)&r;
}

// ---------------------------------------------------------------------------
// Kernel A: dual projection GEMM on tensor cores (m16n8k16 f16, f32 accum).
// Block tile 128x128, 8 warps of 32x64. (unchanged from R8 — verified)
// ---------------------------------------------------------------------------
__global__ void __launch_bounds__(256, 1) proj_kernel(
    const float* __restrict__ Aq, const float* __restrict__ Ak,
    const float* __restrict__ Wq, const float* __restrict__ Wk)
{
    const int z = blockIdx.z;
    const float* __restrict__ A = z ? Ak : Aq;
    const float* __restrict__ W = z ? Wk : Wq;
    __half* __restrict__ out = z ? g_kproj : g_qproj;

    __shared__ __half As[128 * 24];   // [row][k] stride 24
    __shared__ __half Bs[128 * 24];   // [n][k]   stride 24 (transposed W tile)

    const int tid  = threadIdx.x;
    const int wid  = tid >> 5, lane = tid & 31;
    const int m0   = blockIdx.x * 128;
    const int n0   = blockIdx.y * 128;
    const int wm   = (wid & 3) * 32;
    const int wn   = (wid >> 2) * 64;

    const int arow = tid >> 1, acol = (tid & 1) * 8;
    const int bk   = tid >> 4, bn   = (tid & 15) * 8;

    const uint32_t as_base = (uint32_t)__cvta_generic_to_shared(As);
    const uint32_t bs_base = (uint32_t)__cvta_generic_to_shared(Bs);

    float4 a0v = *(const float4*)&A[(m0 + arow) * 256 + acol];
    float4 a1v = *(const float4*)&A[(m0 + arow) * 256 + acol + 4];
    float4 b0v = *(const float4*)&W[bk * 256 + n0 + bn];
    float4 b1v = *(const float4*)&W[bk * 256 + n0 + bn + 4];

    float acc[2][8][4];
#pragma unroll
    for (int mi = 0; mi < 2; mi++)
#pragma unroll
        for (int ni = 0; ni < 8; ni++)
#pragma unroll
            for (int t = 0; t < 4; t++) acc[mi][ni][t] = 0.f;

#pragma unroll 1
    for (int ks = 0; ks < 16; ks++) {
        {
            __half2 ah[4];
            ah[0] = __floats2half2_rn(a0v.x, a0v.y);
            ah[1] = __floats2half2_rn(a0v.z, a0v.w);
            ah[2] = __floats2half2_rn(a1v.x, a1v.y);
            ah[3] = __floats2half2_rn(a1v.z, a1v.w);
            *(uint4*)&As[arow * 24 + acol] = *(uint4*)ah;

            float bf[8] = {b0v.x, b0v.y, b0v.z, b0v.w,
                           b1v.x, b1v.y, b1v.z, b1v.w};
#pragma unroll
            for (int j = 0; j < 8; j++)
                Bs[(bn + j) * 24 + bk] = __float2half_rn(bf[j]);
        }
        __syncthreads();

        if (ks < 15) {
            const int kk = (ks + 1) * 16;
            a0v = *(const float4*)&A[(m0 + arow) * 256 + kk + acol];
            a1v = *(const float4*)&A[(m0 + arow) * 256 + kk + acol + 4];
            b0v = *(const float4*)&W[(kk + bk) * 256 + n0 + bn];
            b1v = *(const float4*)&W[(kk + bk) * 256 + n0 + bn + 4];
        }

        uint32_t af[2][4];
#pragma unroll
        for (int mi = 0; mi < 2; mi++) {
            uint32_t addr = as_base +
                ((wm + mi * 16 + (lane & 15)) * 24 + (lane >> 4) * 8) * 2;
            asm volatile(
                "ldmatrix.sync.aligned.m8n8.x4.shared.b16 {%0,%1,%2,%3}, [%4];"
                : "=r"(af[mi][0]), "=r"(af[mi][1]),
                  "=r"(af[mi][2]), "=r"(af[mi][3]) : "r"(addr));
        }
        uint32_t bf[8][2];
#pragma unroll
        for (int g = 0; g < 4; g++) {
            uint32_t addr = bs_base +
                ((wn + g * 16 + ((lane >> 4) << 3) + (lane & 7)) * 24 +
                 ((lane >> 3) & 1) * 8) * 2;
            uint32_t r0, r1, r2, r3;
            asm volatile(
                "ldmatrix.sync.aligned.m8n8.x4.shared.b16 {%0,%1,%2,%3}, [%4];"
                : "=r"(r0), "=r"(r1), "=r"(r2), "=r"(r3) : "r"(addr));
            bf[g * 2 + 0][0] = r0; bf[g * 2 + 0][1] = r1;
            bf[g * 2 + 1][0] = r2; bf[g * 2 + 1][1] = r3;
        }
#pragma unroll
        for (int mi = 0; mi < 2; mi++)
#pragma unroll
            for (int ni = 0; ni < 8; ni++) {
                asm volatile(
                    "mma.sync.aligned.m16n8k16.row.col.f32.f16.f16.f32 "
                    "{%0,%1,%2,%3}, {%4,%5,%6,%7}, {%8,%9}, {%0,%1,%2,%3};"
                    : "+f"(acc[mi][ni][0]), "+f"(acc[mi][ni][1]),
                      "+f"(acc[mi][ni][2]), "+f"(acc[mi][ni][3])
                    : "r"(af[mi][0]), "r"(af[mi][1]),
                      "r"(af[mi][2]), "r"(af[mi][3]),
                      "r"(bf[ni][0]), "r"(bf[ni][1]));
            }
        __syncthreads();
    }

#pragma unroll
    for (int mi = 0; mi < 2; mi++)
#pragma unroll
        for (int ni = 0; ni < 8; ni++) {
            const int row = m0 + wm + mi * 16 + (lane >> 2);
            const int col = n0 + wn + ni * 8 + (lane & 3) * 2;
            *(__half2*)&out[row * 256 + col] =
                __floats2half2_rn(acc[mi][ni][0], acc[mi][ni][1]);
            *(__half2*)&out[(row + 8) * 256 + col] =
                __floats2half2_rn(acc[mi][ni][2], acc[mi][ni][3]);
        }
}

// ---------------------------------------------------------------------------
// Kernel B: fused scores + mask + softmax + attn@V.
// Score-phase load balancing: vp = ceil32(vlen); replication r = largest pow2
// with vp*r <= 256. Thread = (column tid%vp, h-slice tid/vp), each slice
// covers 32/r chunks. Partials -> p_s[qi][tid]; deterministic fixed-order
// combine into s_s. Padding columns compute-and-discard.
// ---------------------------------------------------------------------------
__global__ void __launch_bounds__(256, 4) attn_kernel(
    const float* __restrict__ values, const int* __restrict__ vlens_i32,
    const float* __restrict__ wv, float* __restrict__ out)
{
    const int b  = blockIdx.y;
    const int q0 = blockIdx.x * TQ;
    const int tid = threadIdx.x;

    __shared__ __half2 q_s2[TQ][H2];   // 4 KB
    __shared__ float   p_s[TQ][KN];    // 8 KB  (slice partials, [qi][tid])
    __shared__ float   s_s[TQ][KN];    // 8 KB  (scores -> attn)
    __shared__ __half2 wv_s2[H2];      // 0.5 KB

    // load q tile (already half) + wv
    const uint4* qbase = (const uint4*)(g_qproj + (b * QN + q0) * HN);
    for (int i = tid; i < TQ * H2 / 4; i += 256)
        ((uint4*)q_s2)[i] = qbase[i];
    for (int i = tid; i < H2; i += 256) {
        float2 v = ((const float2*)wv)[i];
        wv_s2[i] = __float22half2_rn(v);
    }
    __syncthreads();

    const int stride = (vlens_i32[1] == 0) ? 2 : 1;   // int64 vs int32 probe
    const int vlen = vlens_i32[b * stride];

    // ---- work partition: column + h-slice ----
    const int vp = (vlen + 31) & ~31;                 // 32..256
    int r = 256 / vp;                                 // 1..8
    r = (r >= 8) ? 8 : (r >= 4) ? 4 : (r >= 2) ? 2 : 1;
    const bool active = tid < vp * r;
    const int col   = tid % vp;
    const int slice = tid / vp;
    const int cpr   = 32 / r;                         // chunks per slice
    const int c0    = slice * cpr, c1 = c0 + cpr;

    float acc[TQ];
#pragma unroll
    for (int i = 0; i < TQ; i++) acc[i] = 0.f;

    if (active) {
        const uint4* krow = (const uint4*)(g_kproj + (b * KN + col) * HN);

        uint4 kc0 = __ldg(krow + c0);
        uint4 kc1 = __ldg(krow + ((c0 + 1 < c1) ? c0 + 1 : c0));

#pragma unroll 1
        for (int c = c0; c < c1; c++) {
            const int pf = (c + 2 < c1) ? c + 2 : c;
            uint4 kc2 = __ldg(krow + pf);

            __half2 kv2[4];
            kv2[0] = *(__half2*)&kc0.x; kv2[1] = *(__half2*)&kc0.y;
            kv2[2] = *(__half2*)&kc0.z; kv2[3] = *(__half2*)&kc0.w;

            const int hc2 = c * 4;
            __half2 wr2[4];
#pragma unroll
            for (int t = 0; t < 4; t++) wr2[t] = wv_s2[hc2 + t];

#pragma unroll
            for (int qi = 0; qi < TQ; qi++) {
                uint4 qraw = *(const uint4*)&q_s2[qi][hc2];
                __half2 q2[4];
                q2[0] = *(__half2*)&qraw.x; q2[1] = *(__half2*)&qraw.y;
                q2[2] = *(__half2*)&qraw.z; q2[3] = *(__half2*)&qraw.w;
                __half2 a = __float2half2_rn(0.f);
#pragma unroll
                for (int t = 0; t < 4; t++)
                    a = __hfma2(wr2[t], htanh2(__hadd2(q2[t], kv2[t])), a);
                float2 f = __half22float2(a);
                acc[qi] += f.x + f.y;
            }
            kc0 = kc1;
            kc1 = kc2;
        }
    }

    // stash slice partials ([qi][tid]: conflict-free, lane-consecutive)
#pragma unroll
    for (int qi = 0; qi < TQ; qi++) p_s[qi][tid] = acc[qi];
    __syncthreads();

    // ---- deterministic combine + mask: thread kj = tid owns column kj ----
    {
        const int kj = tid;
        if (kj < vlen) {
            float s[TQ];
#pragma unroll
            for (int qi = 0; qi < TQ; qi++) s[qi] = p_s[qi][kj];
            for (int sl = 1; sl < r; sl++) {
                const int idx = kj + sl * vp;
#pragma unroll
                for (int qi = 0; qi < TQ; qi++) s[qi] += p_s[qi][idx];
            }
#pragma unroll
            for (int qi = 0; qi < TQ; qi++) s_s[qi][kj] = s[qi];
        } else {
#pragma unroll
            for (int qi = 0; qi < TQ; qi++) s_s[qi][kj] = -1e6f;
        }
    }
    __syncthreads();

    // ---- softmax: warp w handles row w ----
    const int w = tid >> 5, lane = tid & 31;
    {
        const int rr = w;
        float vals[8];
        float vmax = -1e30f;
#pragma unroll
        for (int t = 0; t < 8; t++) {
            vals[t] = s_s[rr][lane + t * 32];
            vmax = fmaxf(vmax, vals[t]);
        }
#pragma unroll
        for (int off = 16; off; off >>= 1)
            vmax = fmaxf(vmax, __shfl_xor_sync(0xFFFFFFFFu, vmax, off));
        float vsum = 0.f;
#pragma unroll
        for (int t = 0; t < 8; t++) {
            vals[t] = __expf(vals[t] - vmax);
            vsum += vals[t];
        }
#pragma unroll
        for (int off = 16; off; off >>= 1)
            vsum += __shfl_xor_sync(0xFFFFFFFFu, vsum, off);
        const float inv = 1.f / vsum;
#pragma unroll
        for (int t = 0; t < 8; t++)
            s_s[rr][lane + t * 32] = vals[t] * inv;
    }
    __syncthreads();

    // ---- attn @ values: thread owns column d = tid; double-buffered MLP=8 ----
    const int d = tid;
    const int kend = (vlen + 7) & ~7;              // vlen >= 1 so kend >= 8
    const float* vb = values + b * KN * DN + d;
    float o[TQ];
#pragma unroll
    for (int i = 0; i < TQ; i++) o[i] = 0.f;

    float v[8], vn[8];
#pragma unroll
    for (int t = 0; t < 8; t++) v[t] = __ldg(vb + t * DN);

#pragma unroll 1
    for (int k = 0; k < kend; k += 8) {
        const int nk = (k + 8 < kend) ? k + 8 : k;
#pragma unroll
        for (int t = 0; t < 8; t++) vn[t] = __ldg(vb + (nk + t) * DN);
#pragma unroll
        for (int t = 0; t < 8; t++) {
#pragma unroll
            for (int qi = 0; qi < TQ; qi++) o[qi] += s_s[qi][k + t] * v[t];
        }
#pragma unroll
        for (int t = 0; t < 8; t++) v[t] = vn[t];
    }
    float* ob = out + (b * QN + q0) * DN + d;
#pragma unroll
    for (int qi = 0; qi < TQ; qi++) ob[qi * DN] = o[qi];
}

// ---------------------------------------------------------------------------
extern "C" void kernel_launch(void* const* d_in, const int* in_sizes, int n_in,
                              void* d_out, int out_size)
{
    const float* queries = (const float*)d_in[0];
    const float* keys    = (const float*)d_in[1];
    const float* values  = (const float*)d_in[2];
    const int*   vlens   = (const int*)d_in[3];
    const float* Wq      = (const float*)d_in[4];
    const float* Wk      = (const float*)d_in[5];
    const float* wv      = (const float*)d_in[6];
    float*       out     = (float*)d_out;

    dim3 gA(32, 2, 2);               // (4096/128, 256/128, {q,k}) = 128 blocks
    proj_kernel<<<gA, 256>>>(queries, keys, Wq, Wk);

    dim3 gB(QN / TQ, BN);            // (32, 16) = 512 blocks
    attn_kernel<<<gB, 256>>>(values, vlens, wv, out);
}

// round 11
// speedup vs baseline: 1.0103x; 1.0103x over previous
#include <cuda_runtime.h>
#include <cuda_fp16.h>
#include <cstdint>

#define BN 16
#define QN 256
#define KN 256
#define DN 256
#define HN 256
#define TQ 8
#define H2 (HN/2)

// scratch (device globals: no allocation allowed) — both projections half,
// row-major [row][h] with h contiguous (q row = (b,q), k row = (b,kj)).
__device__ __half g_qproj[BN * QN * HN];
__device__ __half g_kproj[BN * KN * HN];

__device__ __forceinline__ __half2 htanh2(__half2 x) {
    unsigned r, xi = *(unsigned*)&x;
    asm("tanh.approx.f16x2 %0, %1;" : "=r"(r) : "r"(xi));
    return *(__half2*)&r;
}

// ---------------------------------------------------------------------------
// Kernel A: dual projection GEMM on tensor cores (m16n8k16 f16, f32 accum).
// Block tile 128x128, 8 warps of 32x64. (unchanged — verified at R8)
// ---------------------------------------------------------------------------
__global__ void __launch_bounds__(256, 1) proj_kernel(
    const float* __restrict__ Aq, const float* __restrict__ Ak,
    const float* __restrict__ Wq, const float* __restrict__ Wk)
{
    const int z = blockIdx.z;
    const float* __restrict__ A = z ? Ak : Aq;
    const float* __restrict__ W = z ? Wk : Wq;
    __half* __restrict__ out = z ? g_kproj : g_qproj;

    __shared__ __half As[128 * 24];   // [row][k] stride 24
    __shared__ __half Bs[128 * 24];   // [n][k]   stride 24 (transposed W tile)

    const int tid  = threadIdx.x;
    const int wid  = tid >> 5, lane = tid & 31;
    const int m0   = blockIdx.x * 128;
    const int n0   = blockIdx.y * 128;
    const int wm   = (wid & 3) * 32;
    const int wn   = (wid >> 2) * 64;

    const int arow = tid >> 1, acol = (tid & 1) * 8;
    const int bk   = tid >> 4, bn   = (tid & 15) * 8;

    const uint32_t as_base = (uint32_t)__cvta_generic_to_shared(As);
    const uint32_t bs_base = (uint32_t)__cvta_generic_to_shared(Bs);

    float4 a0v = *(const float4*)&A[(m0 + arow) * 256 + acol];
    float4 a1v = *(const float4*)&A[(m0 + arow) * 256 + acol + 4];
    float4 b0v = *(const float4*)&W[bk * 256 + n0 + bn];
    float4 b1v = *(const float4*)&W[bk * 256 + n0 + bn + 4];

    float acc[2][8][4];
#pragma unroll
    for (int mi = 0; mi < 2; mi++)
#pragma unroll
        for (int ni = 0; ni < 8; ni++)
#pragma unroll
            for (int t = 0; t < 4; t++) acc[mi][ni][t] = 0.f;

#pragma unroll 1
    for (int ks = 0; ks < 16; ks++) {
        {
            __half2 ah[4];
            ah[0] = __floats2half2_rn(a0v.x, a0v.y);
            ah[1] = __floats2half2_rn(a0v.z, a0v.w);
            ah[2] = __floats2half2_rn(a1v.x, a1v.y);
            ah[3] = __floats2half2_rn(a1v.z, a1v.w);
            *(uint4*)&As[arow * 24 + acol] = *(uint4*)ah;

            float bf[8] = {b0v.x, b0v.y, b0v.z, b0v.w,
                           b1v.x, b1v.y, b1v.z, b1v.w};
#pragma unroll
            for (int j = 0; j < 8; j++)
                Bs[(bn + j) * 24 + bk] = __float2half_rn(bf[j]);
        }
        __syncthreads();

        if (ks < 15) {
            const int kk = (ks + 1) * 16;
            a0v = *(const float4*)&A[(m0 + arow) * 256 + kk + acol];
            a1v = *(const float4*)&A[(m0 + arow) * 256 + kk + acol + 4];
            b0v = *(const float4*)&W[(kk + bk) * 256 + n0 + bn];
            b1v = *(const float4*)&W[(kk + bk) * 256 + n0 + bn + 4];
        }

        uint32_t af[2][4];
#pragma unroll
        for (int mi = 0; mi < 2; mi++) {
            uint32_t addr = as_base +
                ((wm + mi * 16 + (lane & 15)) * 24 + (lane >> 4) * 8) * 2;
            asm volatile(
                "ldmatrix.sync.aligned.m8n8.x4.shared.b16 {%0,%1,%2,%3}, [%4];"
                : "=r"(af[mi][0]), "=r"(af[mi][1]),
                  "=r"(af[mi][2]), "=r"(af[mi][3]) : "r"(addr));
        }
        uint32_t bf[8][2];
#pragma unroll
        for (int g = 0; g < 4; g++) {
            uint32_t addr = bs_base +
                ((wn + g * 16 + ((lane >> 4) << 3) + (lane & 7)) * 24 +
                 ((lane >> 3) & 1) * 8) * 2;
            uint32_t r0, r1, r2, r3;
            asm volatile(
                "ldmatrix.sync.aligned.m8n8.x4.shared.b16 {%0,%1,%2,%3}, [%4];"
                : "=r"(r0), "=r"(r1), "=r"(r2), "=r"(r3) : "r"(addr));
            bf[g * 2 + 0][0] = r0; bf[g * 2 + 0][1] = r1;
            bf[g * 2 + 1][0] = r2; bf[g * 2 + 1][1] = r3;
        }
#pragma unroll
        for (int mi = 0; mi < 2; mi++)
#pragma unroll
            for (int ni = 0; ni < 8; ni++) {
                asm volatile(
                    "mma.sync.aligned.m16n8k16.row.col.f32.f16.f16.f32 "
                    "{%0,%1,%2,%3}, {%4,%5,%6,%7}, {%8,%9}, {%0,%1,%2,%3};"
                    : "+f"(acc[mi][ni][0]), "+f"(acc[mi][ni][1]),
                      "+f"(acc[mi][ni][2]), "+f"(acc[mi][ni][3])
                    : "r"(af[mi][0]), "r"(af[mi][1]),
                      "r"(af[mi][2]), "r"(af[mi][3]),
                      "r"(bf[ni][0]), "r"(bf[ni][1]));
            }
        __syncthreads();
    }

#pragma unroll
    for (int mi = 0; mi < 2; mi++)
#pragma unroll
        for (int ni = 0; ni < 8; ni++) {
            const int row = m0 + wm + mi * 16 + (lane >> 2);
            const int col = n0 + wn + ni * 8 + (lane & 3) * 2;
            *(__half2*)&out[row * 256 + col] =
                __floats2half2_rn(acc[mi][ni][0], acc[mi][ni][1]);
            *(__half2*)&out[(row + 8) * 256 + col] =
                __floats2half2_rn(acc[mi][ni][2], acc[mi][ni][3]);
        }
}

// ---------------------------------------------------------------------------
// Kernel B: fused scores + mask + softmax + attn@V.
// R11: instruction-count cuts. Score: col=tid (balancing reverted), fp16
// accumulation over 2-chunk pairs before f32 promote. AV: s_s read as float4
// (16 LDS.128 per 8-k step instead of 64 LDS.32), v double-buffered.
// ---------------------------------------------------------------------------
__global__ void __launch_bounds__(256, 4) attn_kernel(
    const float* __restrict__ values, const int* __restrict__ vlens_i32,
    const float* __restrict__ wv, float* __restrict__ out)
{
    const int b  = blockIdx.y;
    const int q0 = blockIdx.x * TQ;
    const int tid = threadIdx.x;

    __shared__ __half2 q_s2[TQ][H2];                 // 4 KB
    __shared__ __align__(16) float s_s[TQ][KN];      // 8 KB
    __shared__ __half2 wv_s2[H2];                    // 0.5 KB

    // load q tile (already half) + wv
    const uint4* qbase = (const uint4*)(g_qproj + (b * QN + q0) * HN);
    for (int i = tid; i < TQ * H2 / 4; i += 256)
        ((uint4*)q_s2)[i] = qbase[i];
    for (int i = tid; i < H2; i += 256) {
        float2 v = ((const float2*)wv)[i];
        wv_s2[i] = __float22half2_rn(v);
    }
    __syncthreads();

    const int stride = (vlens_i32[1] == 0) ? 2 : 1;   // int64 vs int32 probe
    const int vlen = vlens_i32[b * stride];

    // ---- score phase: this thread owns column kj = tid ----
    const int kj = tid;
    float acc[TQ];
#pragma unroll
    for (int i = 0; i < TQ; i++) acc[i] = 0.f;

    if (kj < vlen) {
        const uint4* krow = (const uint4*)(g_kproj + (b * KN + kj) * HN);

        uint4 ka = __ldg(krow + 0), kb = __ldg(krow + 1);

#pragma unroll 1
        for (int c = 0; c < 32; c += 2) {            // 2 chunks (16 h) / iter
            const int nc = (c + 2 < 32) ? c + 2 : c;
            uint4 na = __ldg(krow + nc), nb = __ldg(krow + nc + 1);

            __half2 kva[4], kvb[4];
            kva[0] = *(__half2*)&ka.x; kva[1] = *(__half2*)&ka.y;
            kva[2] = *(__half2*)&ka.z; kva[3] = *(__half2*)&ka.w;
            kvb[0] = *(__half2*)&kb.x; kvb[1] = *(__half2*)&kb.y;
            kvb[2] = *(__half2*)&kb.z; kvb[3] = *(__half2*)&kb.w;

            const int hc2 = c * 4;
            __half2 wra[4], wrb[4];
#pragma unroll
            for (int t = 0; t < 4; t++) wra[t] = wv_s2[hc2 + t];
#pragma unroll
            for (int t = 0; t < 4; t++) wrb[t] = wv_s2[hc2 + 4 + t];

#pragma unroll
            for (int qi = 0; qi < TQ; qi++) {
                uint4 qra = *(const uint4*)&q_s2[qi][hc2];
                uint4 qrb = *(const uint4*)&q_s2[qi][hc2 + 4];
                __half2 qa[4], qb[4];
                qa[0] = *(__half2*)&qra.x; qa[1] = *(__half2*)&qra.y;
                qa[2] = *(__half2*)&qra.z; qa[3] = *(__half2*)&qra.w;
                qb[0] = *(__half2*)&qrb.x; qb[1] = *(__half2*)&qrb.y;
                qb[2] = *(__half2*)&qrb.z; qb[3] = *(__half2*)&qrb.w;

                __half2 a = __float2half2_rn(0.f);
#pragma unroll
                for (int t = 0; t < 4; t++)
                    a = __hfma2(wra[t], htanh2(__hadd2(qa[t], kva[t])), a);
#pragma unroll
                for (int t = 0; t < 4; t++)
                    a = __hfma2(wrb[t], htanh2(__hadd2(qb[t], kvb[t])), a);
                float2 f = __half22float2(a);        // promote per 16 h
                acc[qi] += f.x + f.y;
            }
            ka = na; kb = nb;
        }
    }

    // ---- mask + stash scores ----
    const bool live = (kj < vlen);
#pragma unroll
    for (int qi = 0; qi < TQ; qi++)
        s_s[qi][kj] = live ? acc[qi] : -1e6f;
    __syncthreads();

    // ---- softmax: warp w handles row w ----
    const int w = tid >> 5, lane = tid & 31;
    {
        const int r = w;
        float vals[8];
        float vmax = -1e30f;
#pragma unroll
        for (int t = 0; t < 8; t++) {
            vals[t] = s_s[r][lane + t * 32];
            vmax = fmaxf(vmax, vals[t]);
        }
#pragma unroll
        for (int off = 16; off; off >>= 1)
            vmax = fmaxf(vmax, __shfl_xor_sync(0xFFFFFFFFu, vmax, off));
        float vsum = 0.f;
#pragma unroll
        for (int t = 0; t < 8; t++) {
            vals[t] = __expf(vals[t] - vmax);
            vsum += vals[t];
        }
#pragma unroll
        for (int off = 16; off; off >>= 1)
            vsum += __shfl_xor_sync(0xFFFFFFFFu, vsum, off);
        const float inv = 1.f / vsum;
#pragma unroll
        for (int t = 0; t < 8; t++)
            s_s[r][lane + t * 32] = vals[t] * inv;
    }
    __syncthreads();

    // ---- attn @ values: thread owns column d = tid ----
    // s_s rows read as float4 (broadcast LDS.128); v double-buffered MLP=8;
    // k >= vlen has attn == 0 exactly -> loop to vlen rounded up to 8.
    const int d = tid;
    const int kend = (vlen + 7) & ~7;              // vlen >= 1 so kend >= 8
    const float* vb = values + b * KN * DN + d;
    float o[TQ];
#pragma unroll
    for (int i = 0; i < TQ; i++) o[i] = 0.f;

    float v[8], vn[8];
#pragma unroll
    for (int t = 0; t < 8; t++) v[t] = __ldg(vb + t * DN);

#pragma unroll 1
    for (int k = 0; k < kend; k += 8) {
        const int nk = (k + 8 < kend) ? k + 8 : k;
#pragma unroll
        for (int t = 0; t < 8; t++) vn[t] = __ldg(vb + (nk + t) * DN);
#pragma unroll
        for (int qi = 0; qi < TQ; qi++) {
            const float4 sa = *(const float4*)&s_s[qi][k];
            const float4 sb = *(const float4*)&s_s[qi][k + 4];
            o[qi] += sa.x * v[0] + sa.y * v[1] + sa.z * v[2] + sa.w * v[3]
                   + sb.x * v[4] + sb.y * v[5] + sb.z * v[6] + sb.w * v[7];
        }
#pragma unroll
        for (int t = 0; t < 8; t++) v[t] = vn[t];
    }
    float* ob = out + (b * QN + q0) * DN + d;
#pragma unroll
    for (int qi = 0; qi < TQ; qi++) ob[qi * DN] = o[qi];
}

// ---------------------------------------------------------------------------
extern "C" void kernel_launch(void* const* d_in, const int* in_sizes, int n_in,
                              void* d_out, int out_size)
{
    const float* queries = (const float*)d_in[0];
    const float* keys    = (const float*)d_in[1];
    const float* values  = (const float*)d_in[2];
    const int*   vlens   = (const int*)d_in[3];
    const float* Wq      = (const float*)d_in[4];
    const float* Wk      = (const float*)d_in[5];
    const float* wv      = (const float*)d_in[6];
    float*       out     = (float*)d_out;

    dim3 gA(32, 2, 2);               // (4096/128, 256/128, {q,k}) = 128 blocks
    proj_kernel<<<gA, 256>>>(queries, keys, Wq, Wk);

    dim3 gB(QN / TQ, BN);            // (32, 16) = 512 blocks
    attn_kernel<<<gB, 256>>>(values, vlens, wv, out);
}

// round 12
// speedup vs baseline: 1.2187x; 1.2063x over previous
#include <cuda_runtime.h>
#include <cuda_fp16.h>
#include <cstdint>

#define BN 16
#define QN 256
#define KN 256
#define DN 256
#define HN 256
#define TQ 4
#define H2 (HN/2)

// scratch (device globals: no allocation allowed) — both projections half,
// row-major [row][h] with h contiguous (q row = (b,q), k row = (b,kj)).
__device__ __half g_qproj[BN * QN * HN];
__device__ __half g_kproj[BN * KN * HN];

__device__ __forceinline__ __half2 htanh2(__half2 x) {
    unsigned r, xi = *(unsigned*)&x;
    asm("tanh.approx.f16x2 %0, %1;" : "=r"(r) : "r"(xi));
    return *(__half2*)&r;
}

// ---------------------------------------------------------------------------
// Kernel A: dual projection GEMM on tensor cores (m16n8k16 f16, f32 accum).
// Block tile 128x128, 8 warps of 32x64. (unchanged — verified at R8)
// ---------------------------------------------------------------------------
__global__ void __launch_bounds__(256, 1) proj_kernel(
    const float* __restrict__ Aq, const float* __restrict__ Ak,
    const float* __restrict__ Wq, const float* __restrict__ Wk)
{
    const int z = blockIdx.z;
    const float* __restrict__ A = z ? Ak : Aq;
    const float* __restrict__ W = z ? Wk : Wq;
    __half* __restrict__ out = z ? g_kproj : g_qproj;

    __shared__ __half As[128 * 24];   // [row][k] stride 24
    __shared__ __half Bs[128 * 24];   // [n][k]   stride 24 (transposed W tile)

    const int tid  = threadIdx.x;
    const int wid  = tid >> 5, lane = tid & 31;
    const int m0   = blockIdx.x * 128;
    const int n0   = blockIdx.y * 128;
    const int wm   = (wid & 3) * 32;
    const int wn   = (wid >> 2) * 64;

    const int arow = tid >> 1, acol = (tid & 1) * 8;
    const int bk   = tid >> 4, bn   = (tid & 15) * 8;

    const uint32_t as_base = (uint32_t)__cvta_generic_to_shared(As);
    const uint32_t bs_base = (uint32_t)__cvta_generic_to_shared(Bs);

    float4 a0v = *(const float4*)&A[(m0 + arow) * 256 + acol];
    float4 a1v = *(const float4*)&A[(m0 + arow) * 256 + acol + 4];
    float4 b0v = *(const float4*)&W[bk * 256 + n0 + bn];
    float4 b1v = *(const float4*)&W[bk * 256 + n0 + bn + 4];

    float acc[2][8][4];
#pragma unroll
    for (int mi = 0; mi < 2; mi++)
#pragma unroll
        for (int ni = 0; ni < 8; ni++)
#pragma unroll
            for (int t = 0; t < 4; t++) acc[mi][ni][t] = 0.f;

#pragma unroll 1
    for (int ks = 0; ks < 16; ks++) {
        {
            __half2 ah[4];
            ah[0] = __floats2half2_rn(a0v.x, a0v.y);
            ah[1] = __floats2half2_rn(a0v.z, a0v.w);
            ah[2] = __floats2half2_rn(a1v.x, a1v.y);
            ah[3] = __floats2half2_rn(a1v.z, a1v.w);
            *(uint4*)&As[arow * 24 + acol] = *(uint4*)ah;

            float bf[8] = {b0v.x, b0v.y, b0v.z, b0v.w,
                           b1v.x, b1v.y, b1v.z, b1v.w};
#pragma unroll
            for (int j = 0; j < 8; j++)
                Bs[(bn + j) * 24 + bk] = __float2half_rn(bf[j]);
        }
        __syncthreads();

        if (ks < 15) {
            const int kk = (ks + 1) * 16;
            a0v = *(const float4*)&A[(m0 + arow) * 256 + kk + acol];
            a1v = *(const float4*)&A[(m0 + arow) * 256 + kk + acol + 4];
            b0v = *(const float4*)&W[(kk + bk) * 256 + n0 + bn];
            b1v = *(const float4*)&W[(kk + bk) * 256 + n0 + bn + 4];
        }

        uint32_t af[2][4];
#pragma unroll
        for (int mi = 0; mi < 2; mi++) {
            uint32_t addr = as_base +
                ((wm + mi * 16 + (lane & 15)) * 24 + (lane >> 4) * 8) * 2;
            asm volatile(
                "ldmatrix.sync.aligned.m8n8.x4.shared.b16 {%0,%1,%2,%3}, [%4];"
                : "=r"(af[mi][0]), "=r"(af[mi][1]),
                  "=r"(af[mi][2]), "=r"(af[mi][3]) : "r"(addr));
        }
        uint32_t bf[8][2];
#pragma unroll
        for (int g = 0; g < 4; g++) {
            uint32_t addr = bs_base +
                ((wn + g * 16 + ((lane >> 4) << 3) + (lane & 7)) * 24 +
                 ((lane >> 3) & 1) * 8) * 2;
            uint32_t r0, r1, r2, r3;
            asm volatile(
                "ldmatrix.sync.aligned.m8n8.x4.shared.b16 {%0,%1,%2,%3}, [%4];"
                : "=r"(r0), "=r"(r1), "=r"(r2), "=r"(r3) : "r"(addr));
            bf[g * 2 + 0][0] = r0; bf[g * 2 + 0][1] = r1;
            bf[g * 2 + 1][0] = r2; bf[g * 2 + 1][1] = r3;
        }
#pragma unroll
        for (int mi = 0; mi < 2; mi++)
#pragma unroll
            for (int ni = 0; ni < 8; ni++) {
                asm volatile(
                    "mma.sync.aligned.m16n8k16.row.col.f32.f16.f16.f32 "
                    "{%0,%1,%2,%3}, {%4,%5,%6,%7}, {%8,%9}, {%0,%1,%2,%3};"
                    : "+f"(acc[mi][ni][0]), "+f"(acc[mi][ni][1]),
                      "+f"(acc[mi][ni][2]), "+f"(acc[mi][ni][3])
                    : "r"(af[mi][0]), "r"(af[mi][1]),
                      "r"(af[mi][2]), "r"(af[mi][3]),
                      "r"(bf[ni][0]), "r"(bf[ni][1]));
            }
        __syncthreads();
    }

#pragma unroll
    for (int mi = 0; mi < 2; mi++)
#pragma unroll
        for (int ni = 0; ni < 8; ni++) {
            const int row = m0 + wm + mi * 16 + (lane >> 2);
            const int col = n0 + wn + ni * 8 + (lane & 3) * 2;
            *(__half2*)&out[row * 256 + col] =
                __floats2half2_rn(acc[mi][ni][0], acc[mi][ni][1]);
            *(__half2*)&out[(row + 8) * 256 + col] =
                __floats2half2_rn(acc[mi][ni][2], acc[mi][ni][3]);
        }
}

// ---------------------------------------------------------------------------
// Kernel B: fused scores + mask + softmax + attn@V.
// R12: TQ=4 -> 1024 blocks -> 4+ resident blocks/SM (occ ~50%); split fp16
// accumulators per qi (halved HFMA2 chain). Mask-skip + vlen-bounded AV kept.
// ---------------------------------------------------------------------------
__global__ void __launch_bounds__(256, 4) attn_kernel(
    const float* __restrict__ values, const int* __restrict__ vlens_i32,
    const float* __restrict__ wv, float* __restrict__ out)
{
    const int b  = blockIdx.y;
    const int q0 = blockIdx.x * TQ;
    const int tid = threadIdx.x;

    __shared__ __half2 q_s2[TQ][H2];                 // 2 KB
    __shared__ __align__(16) float s_s[TQ][KN];      // 4 KB
    __shared__ __half2 wv_s2[H2];                    // 0.5 KB

    // load q tile (already half) + wv
    const uint4* qbase = (const uint4*)(g_qproj + (b * QN + q0) * HN);
    for (int i = tid; i < TQ * H2 / 4; i += 256)
        ((uint4*)q_s2)[i] = qbase[i];
    for (int i = tid; i < H2; i += 256) {
        float2 v = ((const float2*)wv)[i];
        wv_s2[i] = __float22half2_rn(v);
    }
    __syncthreads();

    const int stride = (vlens_i32[1] == 0) ? 2 : 1;   // int64 vs int32 probe
    const int vlen = vlens_i32[b * stride];

    // ---- score phase: this thread owns column kj = tid ----
    const int kj = tid;
    float acc[TQ];
#pragma unroll
    for (int i = 0; i < TQ; i++) acc[i] = 0.f;

    if (kj < vlen) {
        const uint4* krow = (const uint4*)(g_kproj + (b * KN + kj) * HN);

        uint4 ka = __ldg(krow + 0), kb = __ldg(krow + 1);

#pragma unroll 1
        for (int c = 0; c < 32; c += 2) {            // 2 chunks (16 h) / iter
            const int nc = (c + 2 < 32) ? c + 2 : c;
            uint4 na = __ldg(krow + nc), nb = __ldg(krow + nc + 1);

            __half2 kva[4], kvb[4];
            kva[0] = *(__half2*)&ka.x; kva[1] = *(__half2*)&ka.y;
            kva[2] = *(__half2*)&ka.z; kva[3] = *(__half2*)&ka.w;
            kvb[0] = *(__half2*)&kb.x; kvb[1] = *(__half2*)&kb.y;
            kvb[2] = *(__half2*)&kb.z; kvb[3] = *(__half2*)&kb.w;

            const int hc2 = c * 4;
            __half2 wra[4], wrb[4];
#pragma unroll
            for (int t = 0; t < 4; t++) wra[t] = wv_s2[hc2 + t];
#pragma unroll
            for (int t = 0; t < 4; t++) wrb[t] = wv_s2[hc2 + 4 + t];

#pragma unroll
            for (int qi = 0; qi < TQ; qi++) {
                uint4 qra = *(const uint4*)&q_s2[qi][hc2];
                uint4 qrb = *(const uint4*)&q_s2[qi][hc2 + 4];
                __half2 qa[4], qb[4];
                qa[0] = *(__half2*)&qra.x; qa[1] = *(__half2*)&qra.y;
                qa[2] = *(__half2*)&qra.z; qa[3] = *(__half2*)&qra.w;
                qb[0] = *(__half2*)&qrb.x; qb[1] = *(__half2*)&qrb.y;
                qb[2] = *(__half2*)&qrb.z; qb[3] = *(__half2*)&qrb.w;

                // two independent fp16 accumulators -> half the HFMA2 chain
                __half2 a0 = __float2half2_rn(0.f);
                __half2 a1 = __float2half2_rn(0.f);
#pragma unroll
                for (int t = 0; t < 4; t++)
                    a0 = __hfma2(wra[t], htanh2(__hadd2(qa[t], kva[t])), a0);
#pragma unroll
                for (int t = 0; t < 4; t++)
                    a1 = __hfma2(wrb[t], htanh2(__hadd2(qb[t], kvb[t])), a1);
                float2 f0 = __half22float2(a0);
                float2 f1 = __half22float2(a1);
                acc[qi] += (f0.x + f0.y) + (f1.x + f1.y);
            }
            ka = na; kb = nb;
        }
    }

    // ---- mask + stash scores ----
    const bool live = (kj < vlen);
#pragma unroll
    for (int qi = 0; qi < TQ; qi++)
        s_s[qi][kj] = live ? acc[qi] : -1e6f;
    __syncthreads();

    // ---- softmax: warp w handles row w (warps 0..TQ-1) ----
    const int w = tid >> 5, lane = tid & 31;
    if (w < TQ) {
        const int r = w;
        float vals[8];
        float vmax = -1e30f;
#pragma unroll
        for (int t = 0; t < 8; t++) {
            vals[t] = s_s[r][lane + t * 32];
            vmax = fmaxf(vmax, vals[t]);
        }
#pragma unroll
        for (int off = 16; off; off >>= 1)
            vmax = fmaxf(vmax, __shfl_xor_sync(0xFFFFFFFFu, vmax, off));
        float vsum = 0.f;
#pragma unroll
        for (int t = 0; t < 8; t++) {
            vals[t] = __expf(vals[t] - vmax);
            vsum += vals[t];
        }
#pragma unroll
        for (int off = 16; off; off >>= 1)
            vsum += __shfl_xor_sync(0xFFFFFFFFu, vsum, off);
        const float inv = 1.f / vsum;
#pragma unroll
        for (int t = 0; t < 8; t++)
            s_s[r][lane + t * 32] = vals[t] * inv;
    }
    __syncthreads();

    // ---- attn @ values: thread owns column d = tid ----
    // s_s rows read as float4; v double-buffered MLP=8; k >= vlen skipped
    // (attn weights there are exactly 0).
    const int d = tid;
    const int kend = (vlen + 7) & ~7;              // vlen >= 1 so kend >= 8
    const float* vb = values + b * KN * DN + d;
    float o[TQ];
#pragma unroll
    for (int i = 0; i < TQ; i++) o[i] = 0.f;

    float v[8], vn[8];
#pragma unroll
    for (int t = 0; t < 8; t++) v[t] = __ldg(vb + t * DN);

#pragma unroll 1
    for (int k = 0; k < kend; k += 8) {
        const int nk = (k + 8 < kend) ? k + 8 : k;
#pragma unroll
        for (int t = 0; t < 8; t++) vn[t] = __ldg(vb + (nk + t) * DN);
#pragma unroll
        for (int qi = 0; qi < TQ; qi++) {
            const float4 sa = *(const float4*)&s_s[qi][k];
            const float4 sb = *(const float4*)&s_s[qi][k + 4];
            o[qi] += sa.x * v[0] + sa.y * v[1] + sa.z * v[2] + sa.w * v[3]
                   + sb.x * v[4] + sb.y * v[5] + sb.z * v[6] + sb.w * v[7];
        }
#pragma unroll
        for (int t = 0; t < 8; t++) v[t] = vn[t];
    }
    float* ob = out + (b * QN + q0) * DN + d;
#pragma unroll
    for (int qi = 0; qi < TQ; qi++) ob[qi * DN] = o[qi];
}

// ---------------------------------------------------------------------------
extern "C" void kernel_launch(void* const* d_in, const int* in_sizes, int n_in,
                              void* d_out, int out_size)
{
    const float* queries = (const float*)d_in[0];
    const float* keys    = (const float*)d_in[1];
    const float* values  = (const float*)d_in[2];
    const int*   vlens   = (const int*)d_in[3];
    const float* Wq      = (const float*)d_in[4];
    const float* Wk      = (const float*)d_in[5];
    const float* wv      = (const float*)d_in[6];
    float*       out     = (float*)d_out;

    dim3 gA(32, 2, 2);               // (4096/128, 256/128, {q,k}) = 128 blocks
    proj_kernel<<<gA, 256>>>(queries, keys, Wq, Wk);

    dim3 gB(QN / TQ, BN);            // (64, 16) = 1024 blocks
    attn_kernel<<<gB, 256>>>(values, vlens, wv, out);
}